// round 16
// baseline (speedup 1.0000x reference)
#include <cuda_runtime.h>
#include <cuda_bf16.h>
#include <stdint.h>
#include <math.h>

// Problem constants
#define B_    2
#define QS_   2048
#define MS_   2048
#define KS_   4096      // MS + QS
#define NH_   16
#define HD_   64
#define H_    1024      // NH*HD
#define NKV_  2048      // 2*NH*HD
#define SCALE_ 0.125f   // 1/sqrt(64)
#define CS_   0.18033688f   // SCALE * log2(e)

// ---------------------------------------------------------------------------
// Scratch (device globals: no allocations allowed anywhere)
// ---------------------------------------------------------------------------
static __device__ __nv_bfloat16 g_xb  [(size_t)B_ * QS_ * H_];
static __device__ __nv_bfloat16 g_memb[(size_t)B_ * MS_ * H_];
static __device__ __nv_bfloat16 g_Wkvt[(size_t)NKV_ * H_];   // [n][k]
static __device__ __nv_bfloat16 g_Wqt [(size_t)H_ * H_];     // [n][k]
static __device__ __nv_bfloat16 g_Wot [(size_t)H_ * H_];     // [n][k]
static __device__ __nv_bfloat16 g_Kb  [(size_t)B_ * KS_ * H_];  // [b*KS+key][dim]
static __device__ __nv_bfloat16 g_Vt  [(size_t)B_ * KS_ * H_];  // [b][h][dim][key]
static __device__ __nv_bfloat16 g_Qb  [(size_t)B_ * QS_ * H_];
static __device__ __nv_bfloat16 g_attb[(size_t)B_ * QS_ * H_];
static __device__ float         g_pre [(size_t)B_ * QS_ * H_];

// ---------------------------------------------------------------------------
// Helpers
// ---------------------------------------------------------------------------
__device__ __forceinline__ unsigned packbf(float lo, float hi) {
    unsigned d;
    asm("cvt.rn.bf16x2.f32 %0, %1, %2;" : "=r"(d) : "f"(hi), "f"(lo));
    return d;    // lo -> low 16 bits, hi -> high 16 bits
}

__device__ __forceinline__ float ex2f(float x) {
    float y;
    asm("ex2.approx.ftz.f32 %0, %1;" : "=f"(y) : "f"(x));
    return y;
}

__device__ __forceinline__ void mma_bf16(float* d, const unsigned* a,
                                         unsigned b0, unsigned b1)
{
    asm volatile(
        "mma.sync.aligned.m16n8k16.row.col.f32.bf16.bf16.f32 "
        "{%0,%1,%2,%3}, {%4,%5,%6,%7}, {%8,%9}, {%0,%1,%2,%3};\n"
        : "+f"(d[0]), "+f"(d[1]), "+f"(d[2]), "+f"(d[3])
        : "r"(a[0]), "r"(a[1]), "r"(a[2]), "r"(a[3]), "r"(b0), "r"(b1));
}

__device__ __forceinline__ void ldmx4(unsigned* r, unsigned addr) {
    asm volatile(
        "ldmatrix.sync.aligned.m8n8.x4.shared.b16 {%0,%1,%2,%3}, [%4];\n"
        : "=r"(r[0]), "=r"(r[1]), "=r"(r[2]), "=r"(r[3]) : "r"(addr));
}

__device__ __forceinline__ void cp16(unsigned dst_smem, const void* src) {
    asm volatile("cp.async.cg.shared.global [%0], [%1], 16;\n"
                 :: "r"(dst_smem), "l"(src));
}
__device__ __forceinline__ unsigned smem_u32(const void* p) {
    return (unsigned)__cvta_generic_to_shared(p);
}
#define CP_COMMIT() asm volatile("cp.async.commit_group;\n" ::: "memory")
#define CP_WAIT(N)  asm volatile("cp.async.wait_group %0;\n" :: "n"(N) : "memory")

// ---------------------------------------------------------------------------
// Prep kernels (merged): fp32->bf16 copies of x+mem; transposed bf16 weights.
// ---------------------------------------------------------------------------
__global__ __launch_bounds__(256) void convk2(const float* __restrict__ x,
                                              const float* __restrict__ mem)
{
    const float* in = blockIdx.y ? mem : x;
    __nv_bfloat16* out = blockIdx.y ? g_memb : g_xb;
    const size_t i = ((size_t)blockIdx.x * 256 + threadIdx.x) * 4;
    float4 v = *(const float4*)(in + i);
    uint2 u = make_uint2(packbf(v.x, v.y), packbf(v.z, v.w));
    *(uint2*)((unsigned*)out + (i >> 1)) = u;
}

__global__ __launch_bounds__(256) void transkv(const float* __restrict__ W)
{
    __shared__ float t[32][33];
    const int n0 = blockIdx.x * 32, k0 = blockIdx.y * 32;
    const int x = threadIdx.x, y = threadIdx.y;   // block (32, 8)
#pragma unroll
    for (int i = 0; i < 32; i += 8)
        t[y + i][x] = W[(size_t)(k0 + y + i) * NKV_ + n0 + x];
    __syncthreads();
#pragma unroll
    for (int i = 0; i < 32; i += 8)
        g_Wkvt[(size_t)(n0 + y + i) * H_ + k0 + x] = __float2bfloat16(t[x][y + i]);
}

__global__ __launch_bounds__(256) void transqo(const float* __restrict__ Wq,
                                               const float* __restrict__ Wo)
{
    const float* W = blockIdx.z ? Wo : Wq;
    __nv_bfloat16* Wt = blockIdx.z ? g_Wot : g_Wqt;
    __shared__ float t[32][33];
    const int n0 = blockIdx.x * 32, k0 = blockIdx.y * 32;
    const int x = threadIdx.x, y = threadIdx.y;
#pragma unroll
    for (int i = 0; i < 32; i += 8)
        t[y + i][x] = W[(size_t)(k0 + y + i) * H_ + n0 + x];
    __syncthreads();
#pragma unroll
    for (int i = 0; i < 32; i += 8)
        Wt[(size_t)(n0 + y + i) * H_ + k0 + x] = __float2bfloat16(t[x][y + i]);
}

// ---------------------------------------------------------------------------
// bf16 tensor-core GEMM, 3-stage cp.async, 128x128 tile, BK=64.
// 256 threads (8 warps, 2x4 grid, 64x32/warp = 4x4 m16n8 tiles, 4 k16-steps).
// Fragments via ldmatrix.x4, ping-pong prefetched one k-step ahead.
// ---------------------------------------------------------------------------
#define LDAb 72                    // bf16 elems per row (144 B)
#define ROWB 144                   // row bytes
#define ASZb (128 * LDAb)          // elems per stage (per operand)
#define NSTG 3
#define GEMM_SMEM_BYTES (NSTG * 2 * ASZb * 2)   // 110592 B
#define NTG (H_ / 64)
#define KVBLKS ((NKV_ / 128) * ((B_ * KS_) / 128))   // 1024
#define QBLKS  ((H_ / 128) * ((B_ * QS_) / 128))     // 256

// ---- fused KV + Q projection: grid = KVBLKS + QBLKS, mode by blockIdx ----
__global__ __launch_bounds__(256) void qkvgemm()
{
    extern __shared__ __nv_bfloat16 sg[];
    __nv_bfloat16* As = sg;                    // [NSTG][128][72]
    __nv_bfloat16* Bs = sg + NSTG * ASZb;      // [NSTG][128][72]

    const int bid  = blockIdx.x;
    const bool isq = (bid >= KVBLKS);
    int row0, col0;
    if (!isq) { col0 = (bid & 15) * 128; row0 = (bid >> 4) * 128; }
    else { const int r = bid - KVBLKS; col0 = (r & 7) * 128; row0 = (r >> 3) * 128; }

    const int tid  = threadIdx.x;
    const int lane = tid & 31;
    const int wid  = tid >> 5;
    const int wm   = (wid >> 2) * 64;
    const int wn   = (wid & 3) * 32;
    const int g    = lane >> 2;
    const int c    = lane & 3;

    // loaders: thread -> (row ar, 32 consecutive k's at ac)
    const int ar = tid >> 1;
    const int ac = (tid & 1) << 5;
    const __nv_bfloat16* arow;
    if (!isq) {
        const int grow = row0 + ar;
        const int bb = grow >> 12;
        const int s  = grow & (KS_ - 1);
        arow = (s < MS_) ? (g_memb + (size_t)(bb * MS_ + s)         * H_)
                         : (g_xb   + (size_t)(bb * QS_ + (s - MS_)) * H_);
    } else {
        arow = g_xb + (size_t)(row0 + ar) * H_;
    }
    const __nv_bfloat16* Wt = isq ? g_Wqt : g_Wkvt;
    const __nv_bfloat16* wrow = Wt + (size_t)(col0 + ar) * H_;

    const unsigned a_dst0 = smem_u32(As + ar * LDAb + ac);
    const unsigned b_dst0 = smem_u32(Bs + ar * LDAb + ac);

    auto issue = [&](int kt) {
        const int k0 = kt * 64;
        const int buf = kt % NSTG;
        const unsigned ad = a_dst0 + buf * (ASZb * 2);
        const unsigned bd = b_dst0 + buf * (ASZb * 2);
#pragma unroll
        for (int i = 0; i < 4; i++) {
            cp16(ad + i * 16, arow + k0 + ac + i * 8);
            cp16(bd + i * 16, wrow + k0 + ac + i * 8);
        }
    };

    unsigned a_off[4];
#pragma unroll
    for (int mi = 0; mi < 4; mi++)
        a_off[mi] = (wm + mi * 16 + (lane & 15)) * ROWB + ((lane >> 4) << 4);
    unsigned b_off[2];
#pragma unroll
    for (int j = 0; j < 2; j++)
        b_off[j] = (wn + j * 16 + ((lane >> 4) << 3) + (lane & 7)) * ROWB +
                   (((lane >> 3) & 1) << 4);

    const unsigned As_base = smem_u32(As);
    const unsigned Bs_base = smem_u32(Bs);

    float acc[4][4][4] = {};

    issue(0); CP_COMMIT();
    issue(1); CP_COMMIT();

    for (int kt = 0; kt < NTG; kt++) {
        if (kt + 2 < NTG) { issue(kt + 2); CP_COMMIT(); CP_WAIT(2); }
        else if (kt + 1 < NTG) CP_WAIT(1);
        else CP_WAIT(0);
        __syncthreads();

        const unsigned ab = As_base + (kt % NSTG) * (ASZb * 2);
        const unsigned bb = Bs_base + (kt % NSTG) * (ASZb * 2);

        unsigned af[2][4][4], bfr[2][2][4];
#pragma unroll
        for (int mi = 0; mi < 4; mi++) ldmx4(af[0][mi], ab + a_off[mi]);
#pragma unroll
        for (int j = 0; j < 2; j++)   ldmx4(bfr[0][j], bb + b_off[j]);

#pragma unroll
        for (int ks = 0; ks < 4; ks++) {
            const int cur = ks & 1, nxt = cur ^ 1;
            if (ks < 3) {
#pragma unroll
                for (int mi = 0; mi < 4; mi++)
                    ldmx4(af[nxt][mi], ab + a_off[mi] + (ks + 1) * 32);
#pragma unroll
                for (int j = 0; j < 2; j++)
                    ldmx4(bfr[nxt][j], bb + b_off[j] + (ks + 1) * 32);
            }
#pragma unroll
            for (int ni = 0; ni < 4; ni++) {
                const unsigned b0 = bfr[cur][ni >> 1][(ni & 1) * 2 + 0];
                const unsigned b1 = bfr[cur][ni >> 1][(ni & 1) * 2 + 1];
#pragma unroll
                for (int mi = 0; mi < 4; mi++)
                    mma_bf16(acc[mi][ni], af[cur][mi], b0, b1);
            }
        }
        __syncthreads();
    }

    // ---- epilogue ----
#pragma unroll
    for (int mi = 0; mi < 4; mi++) {
#pragma unroll
        for (int half = 0; half < 2; half++) {
            const int row = row0 + wm + mi * 16 + g + half * 8;
#pragma unroll
            for (int ni = 0; ni < 4; ni++) {
                const int col = col0 + wn + ni * 8 + (c << 1);
                const float vx = acc[mi][ni][half * 2 + 0];
                const float vy = acc[mi][ni][half * 2 + 1];
                if (isq) {
                    ((unsigned*)g_Qb)[((size_t)row * H_ + col) >> 1] =
                        packbf(vx, vy);
                } else if (col0 < H_) {
                    ((unsigned*)g_Kb)[((size_t)row * H_ + col) >> 1] =
                        packbf(vx, vy);
                } else {
                    const int vcol = col - H_;
                    const int hh = vcol >> 6, dim = vcol & 63;
                    const int bb2 = row >> 12, key = row & (KS_ - 1);
                    __nv_bfloat16* base = g_Vt +
                        (((size_t)bb2 * NH_ + hh) * 64 + dim) * KS_ + key;
                    base[0]   = __float2bfloat16(vx);
                    base[KS_] = __float2bfloat16(vy);   // dim+1
                }
            }
        }
    }
}

// ---- output projection: g_pre = attb @ Wot + res(=x fp32) ----
__global__ __launch_bounds__(256) void ogemm(const float* __restrict__ res)
{
    extern __shared__ __nv_bfloat16 sg[];
    __nv_bfloat16* As = sg;
    __nv_bfloat16* Bs = sg + NSTG * ASZb;

    const int tid  = threadIdx.x;
    const int lane = tid & 31;
    const int wid  = tid >> 5;
    const int wm   = (wid >> 2) * 64;
    const int wn   = (wid & 3) * 32;
    const int g    = lane >> 2;
    const int c    = lane & 3;
    const int row0 = blockIdx.y * 128;
    const int col0 = blockIdx.x * 128;

    const int ar = tid >> 1;
    const int ac = (tid & 1) << 5;
    const __nv_bfloat16* arow = g_attb + (size_t)(row0 + ar) * H_;
    const __nv_bfloat16* wrow = g_Wot + (size_t)(col0 + ar) * H_;

    const unsigned a_dst0 = smem_u32(As + ar * LDAb + ac);
    const unsigned b_dst0 = smem_u32(Bs + ar * LDAb + ac);

    auto issue = [&](int kt) {
        const int k0 = kt * 64;
        const int buf = kt % NSTG;
        const unsigned ad = a_dst0 + buf * (ASZb * 2);
        const unsigned bd = b_dst0 + buf * (ASZb * 2);
#pragma unroll
        for (int i = 0; i < 4; i++) {
            cp16(ad + i * 16, arow + k0 + ac + i * 8);
            cp16(bd + i * 16, wrow + k0 + ac + i * 8);
        }
    };

    unsigned a_off[4];
#pragma unroll
    for (int mi = 0; mi < 4; mi++)
        a_off[mi] = (wm + mi * 16 + (lane & 15)) * ROWB + ((lane >> 4) << 4);
    unsigned b_off[2];
#pragma unroll
    for (int j = 0; j < 2; j++)
        b_off[j] = (wn + j * 16 + ((lane >> 4) << 3) + (lane & 7)) * ROWB +
                   (((lane >> 3) & 1) << 4);

    const unsigned As_base = smem_u32(As);
    const unsigned Bs_base = smem_u32(Bs);

    float acc[4][4][4] = {};

    issue(0); CP_COMMIT();
    issue(1); CP_COMMIT();

    for (int kt = 0; kt < NTG; kt++) {
        if (kt + 2 < NTG) { issue(kt + 2); CP_COMMIT(); CP_WAIT(2); }
        else if (kt + 1 < NTG) CP_WAIT(1);
        else CP_WAIT(0);
        __syncthreads();

        const unsigned ab = As_base + (kt % NSTG) * (ASZb * 2);
        const unsigned bb = Bs_base + (kt % NSTG) * (ASZb * 2);

        unsigned af[2][4][4], bfr[2][2][4];
#pragma unroll
        for (int mi = 0; mi < 4; mi++) ldmx4(af[0][mi], ab + a_off[mi]);
#pragma unroll
        for (int j = 0; j < 2; j++)   ldmx4(bfr[0][j], bb + b_off[j]);

#pragma unroll
        for (int ks = 0; ks < 4; ks++) {
            const int cur = ks & 1, nxt = cur ^ 1;
            if (ks < 3) {
#pragma unroll
                for (int mi = 0; mi < 4; mi++)
                    ldmx4(af[nxt][mi], ab + a_off[mi] + (ks + 1) * 32);
#pragma unroll
                for (int j = 0; j < 2; j++)
                    ldmx4(bfr[nxt][j], bb + b_off[j] + (ks + 1) * 32);
            }
#pragma unroll
            for (int ni = 0; ni < 4; ni++) {
                const unsigned b0 = bfr[cur][ni >> 1][(ni & 1) * 2 + 0];
                const unsigned b1 = bfr[cur][ni >> 1][(ni & 1) * 2 + 1];
#pragma unroll
                for (int mi = 0; mi < 4; mi++)
                    mma_bf16(acc[mi][ni], af[cur][mi], b0, b1);
            }
        }
        __syncthreads();
    }

#pragma unroll
    for (int mi = 0; mi < 4; mi++) {
#pragma unroll
        for (int half = 0; half < 2; half++) {
            const int row = row0 + wm + mi * 16 + g + half * 8;
#pragma unroll
            for (int ni = 0; ni < 4; ni++) {
                const int col = col0 + wn + ni * 8 + (c << 1);
                float2 r2 = *(const float2*)(res + (size_t)row * H_ + col);
                float2 v = make_float2(acc[mi][ni][half * 2 + 0] + r2.x,
                                       acc[mi][ni][half * 2 + 1] + r2.y);
                *(float2*)&g_pre[(size_t)row * H_ + col] = v;
            }
        }
    }
}

// ---------------------------------------------------------------------------
// bf16 tensor-core flash attention, 2-stage cp.async K/V pipeline,
// ldmatrix fragment loads, exp2-folded softmax (unchanged from round 15).
// ---------------------------------------------------------------------------
#define LDq 72
#define KTSZ (64 * LDq)
#define ATTN_SMEM_BYTES ((128 * LDq + 4 * KTSZ) * 2)

__global__ __launch_bounds__(128) void attn_mma()
{
    extern __shared__ __nv_bfloat16 sa[];
    __nv_bfloat16* Qs  = sa;                        // [128][72]
    __nv_bfloat16* Ksm = sa + 128 * LDq;            // [2][64][72]
    __nv_bfloat16* Vts = sa + 128 * LDq + 2 * KTSZ; // [2][64][72]

    const int tid  = threadIdx.x;
    const int lane = tid & 31;
    const int wq   = tid >> 5;
    const int g    = lane >> 2;
    const int c    = lane & 3;
    const int qt   = gridDim.x - 1 - blockIdx.x;
    const int h    = blockIdx.y, b = blockIdx.z;
    const int q0   = qt * 128;
    const int row_base = q0 + wq * 32;

    const __nv_bfloat16* qb = g_Qb + (size_t)(b * QS_ + q0) * H_ + h * HD_;
    {
        const unsigned qd = smem_u32(Qs + tid * LDq);
#pragma unroll
        for (int i = 0; i < 8; i++)
            cp16(qd + i * 16, qb + (size_t)tid * H_ + i * 8);
    }

    const int lr = tid >> 1;
    const int lc = (tid & 1) << 5;
    const __nv_bfloat16* kb  = g_Kb + (size_t)(b * KS_) * H_ + h * HD_;
    const __nv_bfloat16* vtb = g_Vt +
        (((size_t)b * NH_ + h) * 64 + lr) * KS_;
    const unsigned kd0 = smem_u32(Ksm + lr * LDq + lc);
    const unsigned vd0 = smem_u32(Vts + lr * LDq + lc);

    auto issue_kv = [&](int t, int buf) {
        const int t0 = t * 64;
        const unsigned kd = kd0 + buf * (KTSZ * 2);
        const unsigned vd = vd0 + buf * (KTSZ * 2);
#pragma unroll
        for (int i = 0; i < 4; i++) {
            cp16(kd + i * 16, kb + (size_t)(t0 + lr) * H_ + lc + i * 8);
            cp16(vd + i * 16, vtb + t0 + lc + i * 8);
        }
    };

    issue_kv(0, 0);
    CP_COMMIT();

    unsigned q_off[2];
#pragma unroll
    for (int mi = 0; mi < 2; mi++)
        q_off[mi] = (wq * 32 + mi * 16 + (lane & 15)) * ROWB +
                    ((lane >> 4) << 4);
    unsigned n_off[4];
#pragma unroll
    for (int j = 0; j < 4; j++)
        n_off[j] = (j * 16 + ((lane >> 4) << 3) + (lane & 7)) * ROWB +
                   (((lane >> 3) & 1) << 4);

    const unsigned Qs_base = smem_u32(Qs);
    const unsigned Ks_base = smem_u32(Ksm);
    const unsigned Vs_base = smem_u32(Vts);

    // softmax state tracked in UNSCALED score domain
    float mR[2][2], lR[2][2];
#pragma unroll
    for (int mi = 0; mi < 2; mi++) {
        mR[mi][0] = -1e30f; mR[mi][1] = -1e30f;
        lR[mi][0] = 0.f;    lR[mi][1] = 0.f;
    }
    float o[2][8][4] = {};

    const int limit = min(KS_, q0 + 128 + MS_);
    const int NT = limit / 64;

    for (int t = 0; t < NT; t++) {
        if (t + 1 < NT) {
            issue_kv(t + 1, (t + 1) & 1);
            CP_COMMIT();
            CP_WAIT(1);
        } else {
            CP_WAIT(0);
        }
        __syncthreads();

        const unsigned kbse = Ks_base + (t & 1) * (KTSZ * 2);
        const unsigned vbse = Vs_base + (t & 1) * (KTSZ * 2);
        const int t0 = t * 64;

        float s[2][8][4] = {};
#pragma unroll
        for (int ks = 0; ks < 4; ks++) {
            unsigned a[2][4], kf[4][4];
#pragma unroll
            for (int mi = 0; mi < 2; mi++)
                ldmx4(a[mi], Qs_base + q_off[mi] + ks * 32);
#pragma unroll
            for (int j = 0; j < 4; j++)
                ldmx4(kf[j], kbse + n_off[j] + ks * 32);
#pragma unroll
            for (int nt = 0; nt < 8; nt++) {
                const unsigned b0 = kf[nt >> 1][(nt & 1) * 2 + 0];
                const unsigned b1 = kf[nt >> 1][(nt & 1) * 2 + 1];
                mma_bf16(s[0][nt], a[0], b0, b1);
                mma_bf16(s[1][nt], a[1], b0, b1);
            }
        }

        const bool full = (t0 + 63 <= q0 + MS_);

#pragma unroll
        for (int mi = 0; mi < 2; mi++) {
            const int r0 = row_base + mi * 16 + g;
            const int r1 = r0 + 8;
            if (!full) {
#pragma unroll
                for (int nt = 0; nt < 8; nt++) {
                    const int k0i = t0 + nt * 8 + (c << 1);
                    if (k0i     > r0 + MS_) s[mi][nt][0] = -1e30f;
                    if (k0i + 1 > r0 + MS_) s[mi][nt][1] = -1e30f;
                    if (k0i     > r1 + MS_) s[mi][nt][2] = -1e30f;
                    if (k0i + 1 > r1 + MS_) s[mi][nt][3] = -1e30f;
                }
            }
            float mx0 = -1e30f, mx1 = -1e30f;
#pragma unroll
            for (int nt = 0; nt < 8; nt++) {
                mx0 = fmaxf(mx0, fmaxf(s[mi][nt][0], s[mi][nt][1]));
                mx1 = fmaxf(mx1, fmaxf(s[mi][nt][2], s[mi][nt][3]));
            }
            mx0 = fmaxf(mx0, __shfl_xor_sync(0xffffffffu, mx0, 1));
            mx0 = fmaxf(mx0, __shfl_xor_sync(0xffffffffu, mx0, 2));
            mx1 = fmaxf(mx1, __shfl_xor_sync(0xffffffffu, mx1, 1));
            mx1 = fmaxf(mx1, __shfl_xor_sync(0xffffffffu, mx1, 2));

            const float mn0 = fmaxf(mR[mi][0], mx0);
            const float mn1 = fmaxf(mR[mi][1], mx1);
            const float sc0 = ex2f((mR[mi][0] - mn0) * CS_);
            const float sc1 = ex2f((mR[mi][1] - mn1) * CS_);
            mR[mi][0] = mn0; mR[mi][1] = mn1;
            const float nb0 = -mn0 * CS_;
            const float nb1 = -mn1 * CS_;

            float rs0 = 0.f, rs1 = 0.f;
#pragma unroll
            for (int nt = 0; nt < 8; nt++) {
                const float p0 = ex2f(fmaf(s[mi][nt][0], CS_, nb0));
                const float p1 = ex2f(fmaf(s[mi][nt][1], CS_, nb0));
                const float p2 = ex2f(fmaf(s[mi][nt][2], CS_, nb1));
                const float p3 = ex2f(fmaf(s[mi][nt][3], CS_, nb1));
                rs0 += p0 + p1;
                rs1 += p2 + p3;
                s[mi][nt][0] = p0; s[mi][nt][1] = p1;
                s[mi][nt][2] = p2; s[mi][nt][3] = p3;
                o[mi][nt][0] *= sc0; o[mi][nt][1] *= sc0;
                o[mi][nt][2] *= sc1; o[mi][nt][3] *= sc1;
            }
            rs0 += __shfl_xor_sync(0xffffffffu, rs0, 1);
            rs0 += __shfl_xor_sync(0xffffffffu, rs0, 2);
            rs1 += __shfl_xor_sync(0xffffffffu, rs1, 1);
            rs1 += __shfl_xor_sync(0xffffffffu, rs1, 2);
            lR[mi][0] = lR[mi][0] * sc0 + rs0;
            lR[mi][1] = lR[mi][1] * sc1 + rs1;
        }

#pragma unroll
        for (int kt = 0; kt < 4; kt++) {
            unsigned a[2][4], vf[4][4];
#pragma unroll
            for (int mi = 0; mi < 2; mi++) {
                a[mi][0] = packbf(s[mi][2*kt][0],     s[mi][2*kt][1]);
                a[mi][1] = packbf(s[mi][2*kt][2],     s[mi][2*kt][3]);
                a[mi][2] = packbf(s[mi][2*kt + 1][0], s[mi][2*kt + 1][1]);
                a[mi][3] = packbf(s[mi][2*kt + 1][2], s[mi][2*kt + 1][3]);
            }
#pragma unroll
            for (int j = 0; j < 4; j++)
                ldmx4(vf[j], vbse + n_off[j] + kt * 32);
#pragma unroll
            for (int nt = 0; nt < 8; nt++) {
                const unsigned b0 = vf[nt >> 1][(nt & 1) * 2 + 0];
                const unsigned b1 = vf[nt >> 1][(nt & 1) * 2 + 1];
                mma_bf16(o[0][nt], a[0], b0, b1);
                mma_bf16(o[1][nt], a[1], b0, b1);
            }
        }
        __syncthreads();
    }

#pragma unroll
    for (int mi = 0; mi < 2; mi++) {
        const float inv0 = 1.0f / lR[mi][0];
        const float inv1 = 1.0f / lR[mi][1];
        const int r0 = row_base + mi * 16 + g;
#pragma unroll
        for (int nt = 0; nt < 8; nt++) {
            const int col = h * HD_ + nt * 8 + (c << 1);
            ((unsigned*)g_attb)[((size_t)(b * QS_ + r0) * H_ + col) >> 1] =
                packbf(o[mi][nt][0] * inv0, o[mi][nt][1] * inv0);
            ((unsigned*)g_attb)[((size_t)(b * QS_ + r0 + 8) * H_ + col) >> 1] =
                packbf(o[mi][nt][2] * inv1, o[mi][nt][3] * inv1);
        }
    }
}

// ---------------------------------------------------------------------------
// LayerNorm over last dim (1024). One 256-thread block per row.
// ---------------------------------------------------------------------------
__global__ __launch_bounds__(256) void ln_kernel(const float* __restrict__ gam,
                                                 const float* __restrict__ bet,
                                                 float* __restrict__ out)
{
    __shared__ float sb1[8], sb2[8];
    const int tid = threadIdx.x;
    const int row = blockIdx.x;
    const float* r = g_pre + (size_t)row * H_;

    float4 v = *(const float4*)(r + (tid << 2));
    float sum = v.x + v.y + v.z + v.w;
#pragma unroll
    for (int off = 16; off; off >>= 1) sum += __shfl_xor_sync(0xffffffffu, sum, off);
    if ((tid & 31) == 0) sb1[tid >> 5] = sum;
    __syncthreads();
    float mean;
    {
        float t = 0.f;
#pragma unroll
        for (int i = 0; i < 8; i++) t += sb1[i];
        mean = t * (1.0f / H_);
    }

    const float dx0 = v.x - mean, dx1 = v.y - mean;
    const float dx2 = v.z - mean, dx3 = v.w - mean;
    float sq = dx0 * dx0 + dx1 * dx1 + dx2 * dx2 + dx3 * dx3;
#pragma unroll
    for (int off = 16; off; off >>= 1) sq += __shfl_xor_sync(0xffffffffu, sq, off);
    if ((tid & 31) == 0) sb2[tid >> 5] = sq;
    __syncthreads();
    float var;
    {
        float t = 0.f;
#pragma unroll
        for (int i = 0; i < 8; i++) t += sb2[i];
        var = t * (1.0f / H_);
    }
    const float rstd = rsqrtf(var + 1e-5f);

    float4 g4 = *(const float4*)(gam + (tid << 2));
    float4 b4 = *(const float4*)(bet + (tid << 2));
    float4 ov;
    ov.x = dx0 * rstd * g4.x + b4.x;
    ov.y = dx1 * rstd * g4.y + b4.y;
    ov.z = dx2 * rstd * g4.z + b4.z;
    ov.w = dx3 * rstd * g4.w + b4.w;
    *(float4*)(out + (size_t)row * H_ + (tid << 2)) = ov;
}

// ---------------------------------------------------------------------------
// Entry point. Inputs (metadata order): x, mem, mask(unused), W_kv, W_q, W_o,
// ln_g, ln_b. Output: float32 [B, QS, H].
// ---------------------------------------------------------------------------
extern "C" void kernel_launch(void* const* d_in, const int* in_sizes, int n_in,
                              void* d_out, int out_size)
{
    const float* x   = (const float*)d_in[0];
    const float* mem = (const float*)d_in[1];
    // d_in[2] = mask: recomputed analytically (k <= q + MS), never read
    const float* Wkv = (const float*)d_in[3];
    const float* Wq  = (const float*)d_in[4];
    const float* Wo  = (const float*)d_in[5];
    const float* gam = (const float*)d_in[6];
    const float* bet = (const float*)d_in[7];
    float* out = (float*)d_out;

    cudaFuncSetAttribute(qkvgemm, cudaFuncAttributeMaxDynamicSharedMemorySize,
                         GEMM_SMEM_BYTES);
    cudaFuncSetAttribute(ogemm, cudaFuncAttributeMaxDynamicSharedMemorySize,
                         GEMM_SMEM_BYTES);
    cudaFuncSetAttribute(attn_mma, cudaFuncAttributeMaxDynamicSharedMemorySize,
                         ATTN_SMEM_BYTES);

    const int nconv = (B_ * QS_ * H_) / 1024;   // 4096
    convk2<<<dim3(nconv, 2), 256>>>(x, mem);
    transkv<<<dim3(NKV_ / 32, H_ / 32), dim3(32, 8)>>>(Wkv);
    transqo<<<dim3(H_ / 32, H_ / 32, 2), dim3(32, 8)>>>(Wq, Wo);

    qkvgemm<<<KVBLKS + QBLKS, 256, GEMM_SMEM_BYTES>>>();
    attn_mma<<<dim3(QS_ / 128, NH_, B_), 128, ATTN_SMEM_BYTES>>>();
    ogemm<<<dim3(H_ / 128, (B_ * QS_) / 128), 256, GEMM_SMEM_BYTES>>>(x);
    ln_kernel<<<B_ * QS_, 256>>>(gam, bet, out);
}